// round 13
// baseline (speedup 1.0000x reference)
#include <cuda_runtime.h>
#include <cuda_bf16.h>
#include <math.h>
#include <stdint.h>

#define Bn 4
#define Tn 8
#define Hn 256
#define Wn 256
#define Nn (Bn*Tn*Hn*Wn)   // 2,097,152

#define STENCIL_CTAS 2048
#define CONV_CTAS    2048

// AoS params: per point 8 bf16 = 16 B: cc,ce,cw,cs,cn,cx,D,pad
__device__ __nv_bfloat16 g_paramsB[(size_t)Nn * 8];
__device__ float g_partLogD[CONV_CTAS];
__device__ float g_partXQX[STENCIL_CTAS];
// per-lane bf16x2 B fragments, direct-from-global layout:
// g_Wfb2[(lane*5 + step)*20 + e], e in 0..15 used (16..19 pad, never read)
__device__ __align__(16) uint32_t g_Wfb2[32 * 5 * 20];
__device__ unsigned g_ticket;

__device__ __forceinline__ float tanh_fast(float x) {
    float y; asm("tanh.approx.f32 %0, %1;" : "=f"(y) : "f"(x)); return y;
}
__device__ __forceinline__ float sigmoid_fast(float x) {
    return fmaf(0.5f, tanh_fast(0.5f * x), 0.5f);
}
__device__ __forceinline__ void mma_bf16(float c[4],
                                         uint32_t a0, uint32_t a1, uint32_t a2, uint32_t a3,
                                         uint32_t b0, uint32_t b1) {
    asm("mma.sync.aligned.m16n8k16.row.col.f32.bf16.bf16.f32 "
        "{%0,%1,%2,%3}, {%4,%5,%6,%7}, {%8,%9}, {%0,%1,%2,%3};"
        : "+f"(c[0]), "+f"(c[1]), "+f"(c[2]), "+f"(c[3])
        : "r"(a0), "r"(a1), "r"(a2), "r"(a3), "r"(b0), "r"(b1));
}

__device__ __forceinline__ float block_reduce_sum(float v) {
    __shared__ float red[8];
    #pragma unroll
    for (int o = 16; o > 0; o >>= 1) v += __shfl_down_sync(0xffffffffu, v, o);
    int lane = threadIdx.x & 31, wid = threadIdx.x >> 5;
    if (lane == 0) red[wid] = v;
    __syncthreads();
    if (wid == 0) {
        v = (lane < 8) ? red[lane] : 0.f;
        #pragma unroll
        for (int o = 4; o > 0; o >>= 1) v += __shfl_down_sync(0xffffffffu, v, o);
    }
    return v;  // valid on thread 0
}

// ---------------------------------------------------------------------------
// Weight fragment swizzle (bf16x2, tap pairs) + ticket reset.
// word = bf16x2( W[oc][ic=2q][tap], W[oc][ic=2q+1][tap] ), oc = n*8 + (lane>>2)
// tap = step*2 + s (s = e&1), tap 9 = zeros. e = n*2 + s.
// ---------------------------------------------------------------------------
__global__ void precompute_wf_kernel(const float* __restrict__ w) {
    int j = blockIdx.x * 256 + threadIdx.x;
    if (j == 0) g_ticket = 0;
    if (j < 5 * 32 * 16) {
        int step = j >> 9;
        int r    = j & 511;
        int ln   = r >> 4;
        int e    = r & 15;
        int n    = e >> 1;
        int s    = e & 1;
        int q    = ln & 3;
        int ocg  = ln >> 2;
        int oc   = n * 8 + ocg;
        int tap  = step * 2 + s;
        float w0 = 0.f, w1 = 0.f;
        if (tap < 9) {
            w0 = w[oc * 72 + (2 * q)     * 9 + tap];
            w1 = w[oc * 72 + (2 * q + 1) * 9 + tap];
        }
        __nv_bfloat162 pk = __floats2bfloat162_rn(w0, w1);
        g_Wfb2[(ln * 5 + step) * 20 + e] = *(uint32_t*)&pk;
    }
}

// ---------------------------------------------------------------------------
// Conv 3x3 (8 -> 64 ch), bf16 mma.sync m16n8k16, B frags direct from global
// (L1-resident, no smem staging). AoS bf16 param store.
// CTA: 256 thr / 8 warps. grid (2 w-segs, 256 h, 4 b) = 2048 CTAs.
// ---------------------------------------------------------------------------
__global__ __launch_bounds__(256)
void conv_mma_kernel(const float* __restrict__ x, const float* __restrict__ w) {
    __shared__ uint32_t xsb[3][4][136];                    // bf16x2 ic-pairs

    const int tid  = threadIdx.x;
    const int lane = tid & 31;
    const int wid  = tid >> 5;
    const int seg  = blockIdx.x;           // 0..1
    const int h    = blockIdx.y;           // 0..255
    const int b    = blockIdx.z;           // 0..3
    const int w0   = seg * 128;

    // ---- stage x slab: 12 rows (kh 0..2 x icpair 0..3) x 130 cols ----
    {
        const float* xb = x + b * Tn * Hn * Wn;
        #pragma unroll
        for (int rr = 0; rr < 2; ++rr) {
            int row = wid + rr * 8;        // 0..15, only <12 valid
            if (row < 12) {
                int kh = row >> 2;
                int p  = row & 3;
                int gh = h - 1 + kh;
                bool hok = (unsigned)gh < (unsigned)Hn;
                const float* rp0 = xb + ((2 * p)     * Hn + gh) * Wn;
                const float* rp1 = xb + ((2 * p + 1) * Hn + gh) * Wn;
                #pragma unroll
                for (int it = 0; it < 5; ++it) {
                    int col = lane + it * 32;
                    if (col < 130) {
                        int gw = w0 - 1 + col;
                        bool ok = hok && (unsigned)gw < (unsigned)Wn;
                        float v0 = ok ? rp0[gw] : 0.f;
                        float v1 = ok ? rp1[gw] : 0.f;
                        __nv_bfloat162 pk = __floats2bfloat162_rn(v0, v1);
                        xsb[kh][p][col] = *(uint32_t*)&pk;
                    }
                }
            }
        }
    }
    __syncthreads();

    // ---- GEMM: each warp m16 x n64, K=80 (5 k16 steps, last half zero) ----
    const int q  = lane & 3;
    const int m0 = (wid << 4) + (lane >> 2);

    float acc[8][4];
    #pragma unroll
    for (int n = 0; n < 8; ++n)
        #pragma unroll
        for (int c = 0; c < 4; ++c) acc[n][c] = 0.f;

    const uint4* wf_lane = (const uint4*)&g_Wfb2[lane * 100];

    #pragma unroll
    for (int step = 0; step < 5; ++step) {
        const int tap0 = 2 * step;
        const int tap1 = (2 * step + 1 < 9) ? 2 * step + 1 : 8;  // tap9 -> B=0
        const int kh0 = tap0 / 3, kw0 = tap0 % 3;
        const int kh1 = tap1 / 3, kw1 = tap1 % 3;

        uint32_t a0 = xsb[kh0][q][m0 + kw0];
        uint32_t a1 = xsb[kh0][q][m0 + 8 + kw0];
        uint32_t a2 = xsb[kh1][q][m0 + kw1];
        uint32_t a3 = xsb[kh1][q][m0 + 8 + kw1];

        const uint4* wp = wf_lane + step * 5;
        uint4 B0 = wp[0], B1 = wp[1], B2 = wp[2], B3 = wp[3];

        mma_bf16(acc[0], a0, a1, a2, a3, B0.x, B0.y);
        mma_bf16(acc[1], a0, a1, a2, a3, B0.z, B0.w);
        mma_bf16(acc[2], a0, a1, a2, a3, B1.x, B1.y);
        mma_bf16(acc[3], a0, a1, a2, a3, B1.z, B1.w);
        mma_bf16(acc[4], a0, a1, a2, a3, B2.x, B2.y);
        mma_bf16(acc[5], a0, a1, a2, a3, B2.z, B2.w);
        mma_bf16(acc[6], a0, a1, a2, a3, B3.x, B3.y);
        mma_bf16(acc[7], a0, a1, a2, a3, B3.z, B3.w);
    }

    // ---- epilogue: nonlinearities (tanh-based sigmoid) + STG.128 AoS store
    float local_logD = 0.f;
    #pragma unroll
    for (int pi = 0; pi < 2; ++pi) {
        int wglob = w0 + m0 + 8 * pi;
        #pragma unroll
        for (int ti = 0; ti < 2; ++ti) {
            int t = 2 * q + ti;
            int cidx = 2 * pi + ti;
            float a0v = acc[0][cidx];   // kappa
            float a1v = acc[1][cidx];   // m1
            float a2v = acc[2][cidx];   // m2
            float a3v = acc[3][cidx];   // Hxx
            float a4v = acc[4][cidx];   // Hxy
            float a5v = acc[5][cidx];   // Hyx
            float a6v = acc[6][cidx];   // Hyy
            float a7v = acc[7][cidx];   // tau

            float kap  = 0.99f * sigmoid_fast(a0v) + 0.01f;
            float kap2 = kap * kap;
            float hxx  = 0.99f * sigmoid_fast(a3v) + 0.01f;
            float hyy  = 0.99f * sigmoid_fast(a6v) + 0.01f;
            float hxys = 0.1f * (tanh_fast(a4v) + tanh_fast(a5v));
            float tau  = 9.9f * sigmoid_fast(a7v) + 0.1f;
            float Dv   = 1.f / (tau * tau);
            local_logD += -2.f * __logf(tau);

            float cc = kap2 + 2.f * hxx + 2.f * hyy;
            float ce =  0.5f * a1v - hxx;
            float cw = -0.5f * a1v - hxx;
            float cs =  0.5f * a2v - hyy;
            float cn = -0.5f * a2v - hyy;
            float cx = -0.25f * hxys;

            __nv_bfloat162 v0 = __floats2bfloat162_rn(cc, ce);
            __nv_bfloat162 v1 = __floats2bfloat162_rn(cw, cs);
            __nv_bfloat162 v2 = __floats2bfloat162_rn(cn, cx);
            __nv_bfloat162 v3 = __floats2bfloat162_rn(Dv, 0.f);
            uint4 pk;
            pk.x = *(uint32_t*)&v0;
            pk.y = *(uint32_t*)&v1;
            pk.z = *(uint32_t*)&v2;
            pk.w = *(uint32_t*)&v3;

            int idx = ((b * Tn + t) * Hn + h) * Wn + wglob;
            *(uint4*)(g_paramsB + (size_t)idx * 8) = pk;
        }
    }

    __syncthreads();
    float s = block_reduce_sum(local_logD);
    if (tid == 0)
        g_partLogD[(blockIdx.z * 256 + blockIdx.y) * 2 + blockIdx.x] = s;
}

// ---------------------------------------------------------------------------
// Fused double stencil (AoS bf16 params) + last-block final reduction.
// ---------------------------------------------------------------------------
__global__ __launch_bounds__(256)
void fused_stencil_kernel(const float* __restrict__ x, float* __restrict__ out) {
    __shared__ float xs[36][36];
    __shared__ float ys[34][34];

    const int tid = threadIdx.x;
    const int tx  = tid & 31;
    const int ty  = tid >> 5;
    const int bt  = blockIdx.z;        // b*T + t
    const int t   = bt & (Tn - 1);
    const int h0  = blockIdx.y * 32;
    const int w0  = blockIdx.x * 32;
    const int base = bt * Hn * Wn;

    const float* up = x + base;
    for (int i = tid; i < 36 * 36; i += 256) {
        int ly = i / 36, lx = i - ly * 36;
        int gh = h0 - 2 + ly, gw = w0 - 2 + lx;
        xs[ly][lx] = ((unsigned)gh < (unsigned)Hn && (unsigned)gw < (unsigned)Wn)
                         ? up[gh * Wn + gw] : 0.f;
    }
    __syncthreads();

    for (int i = tid; i < 34 * 34; i += 256) {
        int ly = i / 34, lx = i - ly * 34;
        int gh = h0 - 1 + ly, gw = w0 - 1 + lx;
        float yv = 0.f;
        if ((unsigned)gh < (unsigned)Hn && (unsigned)gw < (unsigned)Wn) {
            int gidx = base + gh * Wn + gw;
            uint4 pk = *(const uint4*)(g_paramsB + (size_t)gidx * 8);
            float2 f0 = __bfloat1622float2(*(__nv_bfloat162*)&pk.x);   // cc, ce
            float2 f1 = __bfloat1622float2(*(__nv_bfloat162*)&pk.y);   // cw, cs
            float2 f2 = __bfloat1622float2(*(__nv_bfloat162*)&pk.z);   // cn, cx

            float c  = xs[ly + 1][lx + 1];
            float e  = xs[ly + 1][lx + 2];
            float wv = xs[ly + 1][lx + 0];
            float s  = xs[ly + 2][lx + 1];
            float n  = xs[ly + 0][lx + 1];
            float se = xs[ly + 2][lx + 2];
            float ne = xs[ly + 0][lx + 2];
            float sw = xs[ly + 2][lx + 0];
            float nw = xs[ly + 0][lx + 0];

            yv = f0.x * c + f0.y * e + f1.x * wv + f1.y * s + f2.x * n
               + f2.y * (se - ne - sw + nw);
        }
        ys[ly][lx] = yv;
    }
    __syncthreads();

    float local = 0.f;
    #pragma unroll
    for (int r = 0; r < 4; ++r) {
        int iy = ty * 4 + r;
        int gh = h0 + iy, gw = w0 + tx;
        int gidx = base + gh * Wn + gw;
        int ly = iy + 1, lx = tx + 1;

        uint4 pk = *(const uint4*)(g_paramsB + (size_t)gidx * 8);
        float2 f0 = __bfloat1622float2(*(__nv_bfloat162*)&pk.x);   // cc, ce
        float2 f1 = __bfloat1622float2(*(__nv_bfloat162*)&pk.y);   // cw, cs
        float2 f2 = __bfloat1622float2(*(__nv_bfloat162*)&pk.z);   // cn, cx
        float2 f3 = __bfloat1622float2(*(__nv_bfloat162*)&pk.w);   // D, pad

        float c  = ys[ly][lx];
        float e  = ys[ly][lx + 1];
        float wv = ys[ly][lx - 1];
        float s  = ys[ly + 1][lx];
        float n  = ys[ly - 1][lx];
        float se = ys[ly + 1][lx + 1];
        float ne = ys[ly - 1][lx + 1];
        float sw = ys[ly + 1][lx - 1];
        float nw = ys[ly - 1][lx - 1];

        float z = f0.x * c + f0.y * e + f1.x * wv + f1.y * s + f2.x * n
                + f2.y * (se - ne - sw + nw);

        float xc    = xs[iy + 2][tx + 2];
        float xprev = (t > 0) ? x[gidx - Hn * Wn] : 0.f;
        float rr = xc + z - xprev;
        local += f3.x * rr * rr;
    }

    __syncthreads();
    float ssum = block_reduce_sum(local);

    __shared__ bool amLast;
    if (tid == 0) {
        g_partXQX[(blockIdx.z * 8 + blockIdx.y) * 8 + blockIdx.x] = ssum;
        __threadfence();
        unsigned v = atomicAdd(&g_ticket, 1u);
        amLast = (v == STENCIL_CTAS - 1);
    }
    __syncthreads();

    if (amLast) {
        __shared__ double redq[256];
        __shared__ double redl[256];
        double xq = 0.0, ld = 0.0;
        #pragma unroll
        for (int j = 0; j < STENCIL_CTAS / 256; ++j)
            xq += (double)g_partXQX[tid + 256 * j];
        #pragma unroll
        for (int j = 0; j < CONV_CTAS / 256; ++j)
            ld += (double)g_partLogD[tid + 256 * j];
        redq[tid] = xq;
        redl[tid] = ld;
        __syncthreads();
        #pragma unroll
        for (int o = 128; o > 0; o >>= 1) {
            if (tid < o) {
                redq[tid] += redq[tid + o];
                redl[tid] += redl[tid + o];
            }
            __syncthreads();
        }
        if (tid == 0) out[0] = (float)(0.5 * (redq[0] - redl[0]));
    }
}

extern "C" void kernel_launch(void* const* d_in, const int* in_sizes, int n_in,
                              void* d_out, int out_size) {
    const float* x = (const float*)d_in[0];
    const float* w = (const float*)d_in[1];
    float* out = (float*)d_out;

    precompute_wf_kernel<<<10, 256>>>(w);
    conv_mma_kernel<<<dim3(2, 256, Bn), 256>>>(x, w);
    fused_stencil_kernel<<<dim3(8, 8, Bn * Tn), 256>>>(x, out);
}

// round 14
// speedup vs baseline: 1.1814x; 1.1814x over previous
#include <cuda_runtime.h>
#include <cuda_bf16.h>
#include <math.h>
#include <stdint.h>

#define Bn 4
#define Tn 8
#define Hn 256
#define Wn 256
#define Nn (Bn*Tn*Hn*Wn)   // 2,097,152

#define STENCIL_CTAS 2048
#define CONV_CTAS    2048

// AoS params: per point 8 bf16 = 16 B: cc,ce,cw,cs,cn,cx,D,pad
__device__ __nv_bfloat16 g_paramsB[(size_t)Nn * 8];
__device__ float g_partLogD[CONV_CTAS];
__device__ float g_partXQX[STENCIL_CTAS];
__device__ uint32_t g_Wfb[5 * 32 * 20];  // per-lane bf16x2 B fragments (5 k16 steps)
__device__ unsigned g_ticket;

__device__ __forceinline__ float tanh_fast(float x) {
    float y; asm("tanh.approx.f32 %0, %1;" : "=f"(y) : "f"(x)); return y;
}
__device__ __forceinline__ float sigmoid_fast(float x) {
    return fmaf(0.5f, tanh_fast(0.5f * x), 0.5f);
}
__device__ __forceinline__ void mma_bf16(float c[4],
                                         uint32_t a0, uint32_t a1, uint32_t a2, uint32_t a3,
                                         uint32_t b0, uint32_t b1) {
    asm("mma.sync.aligned.m16n8k16.row.col.f32.bf16.bf16.f32 "
        "{%0,%1,%2,%3}, {%4,%5,%6,%7}, {%8,%9}, {%0,%1,%2,%3};"
        : "+f"(c[0]), "+f"(c[1]), "+f"(c[2]), "+f"(c[3])
        : "r"(a0), "r"(a1), "r"(a2), "r"(a3), "r"(b0), "r"(b1));
}

__device__ __forceinline__ float block_reduce_sum(float v) {
    __shared__ float red[8];
    #pragma unroll
    for (int o = 16; o > 0; o >>= 1) v += __shfl_down_sync(0xffffffffu, v, o);
    int lane = threadIdx.x & 31, wid = threadIdx.x >> 5;
    if (lane == 0) red[wid] = v;
    __syncthreads();
    if (wid == 0) {
        v = (lane < 8) ? red[lane] : 0.f;
        #pragma unroll
        for (int o = 4; o > 0; o >>= 1) v += __shfl_down_sync(0xffffffffu, v, o);
    }
    return v;  // valid on thread 0
}

// ---------------------------------------------------------------------------
// Weight fragment swizzle (bf16x2, tap pairs) + ticket reset. (R12 layout)
// ---------------------------------------------------------------------------
__global__ void precompute_wf_kernel(const float* __restrict__ w) {
    int j = blockIdx.x * 256 + threadIdx.x;
    if (j == 0) g_ticket = 0;
    if (j < 5 * 32 * 16) {
        int step = j >> 9;
        int r    = j & 511;
        int ln   = r >> 4;
        int e    = r & 15;
        int n    = e >> 1;
        int s    = e & 1;
        int q    = ln & 3;
        int ocg  = ln >> 2;
        int oc   = n * 8 + ocg;
        int tap  = step * 2 + s;
        float w0 = 0.f, w1 = 0.f;
        if (tap < 9) {
            w0 = w[oc * 72 + (2 * q)     * 9 + tap];
            w1 = w[oc * 72 + (2 * q + 1) * 9 + tap];
        }
        __nv_bfloat162 pk = __floats2bfloat162_rn(w0, w1);
        g_Wfb[(step * 32 + ln) * 20 + e] = *(uint32_t*)&pk;
    } else if (j < 5 * 32 * 16 + 5 * 32 * 4) {
        int p  = j - 5 * 32 * 16;
        int tl = p >> 2;
        int e  = 16 + (p & 3);
        g_Wfb[tl * 20 + e] = 0;
    }
}

// ---------------------------------------------------------------------------
// Conv 3x3 (8 -> 64 ch), bf16 mma.sync m16n8k16 — R12 known-good mainloop,
// sigmoid_fast epilogue. CTA: 256 thr / 8 warps. grid (2,256,4) = 2048 CTAs.
// ---------------------------------------------------------------------------
__global__ __launch_bounds__(256)
void conv_mma_kernel(const float* __restrict__ x, const float* __restrict__ w) {
    __shared__ uint32_t xsb[3][4][136];                    // bf16x2 ic-pairs
    __shared__ __align__(16) uint32_t Wfb[5 * 32 * 20];    // per-lane B frags

    const int tid  = threadIdx.x;
    const int lane = tid & 31;
    const int wid  = tid >> 5;
    const int seg  = blockIdx.x;           // 0..1
    const int h    = blockIdx.y;           // 0..255
    const int b    = blockIdx.z;           // 0..3
    const int w0   = seg * 128;

    // ---- stage weights: pure linear copy (800 uint4) ----
    {
        const uint4* src = (const uint4*)g_Wfb;
        uint4* dst = (uint4*)Wfb;
        #pragma unroll
        for (int j = 0; j < 4; ++j) {
            int i = tid + j * 256;
            if (i < 800) dst[i] = src[i];
        }
    }

    // ---- stage x slab: 12 rows (kh 0..2 x icpair 0..3) x 130 cols ----
    {
        const float* xb = x + b * Tn * Hn * Wn;
        #pragma unroll
        for (int rr = 0; rr < 2; ++rr) {
            int row = wid + rr * 8;        // 0..15, only <12 valid
            if (row < 12) {
                int kh = row >> 2;
                int p  = row & 3;
                int gh = h - 1 + kh;
                bool hok = (unsigned)gh < (unsigned)Hn;
                const float* rp0 = xb + ((2 * p)     * Hn + gh) * Wn;
                const float* rp1 = xb + ((2 * p + 1) * Hn + gh) * Wn;
                #pragma unroll
                for (int it = 0; it < 5; ++it) {
                    int col = lane + it * 32;
                    if (col < 130) {
                        int gw = w0 - 1 + col;
                        bool ok = hok && (unsigned)gw < (unsigned)Wn;
                        float v0 = ok ? rp0[gw] : 0.f;
                        float v1 = ok ? rp1[gw] : 0.f;
                        __nv_bfloat162 pk = __floats2bfloat162_rn(v0, v1);
                        xsb[kh][p][col] = *(uint32_t*)&pk;
                    }
                }
            }
        }
    }
    __syncthreads();

    // ---- GEMM: each warp m16 x n64, K=80 (5 k16 steps, last half zero) ----
    const int q  = lane & 3;
    const int m0 = (wid << 4) + (lane >> 2);

    float acc[8][4];
    #pragma unroll
    for (int n = 0; n < 8; ++n)
        #pragma unroll
        for (int c = 0; c < 4; ++c) acc[n][c] = 0.f;

    const uint4* wf_lane = (const uint4*)&Wfb[lane * 20];

    #pragma unroll
    for (int step = 0; step < 5; ++step) {
        const int tap0 = 2 * step;
        const int tap1 = (2 * step + 1 < 9) ? 2 * step + 1 : 8;  // tap9 -> B=0
        const int kh0 = tap0 / 3, kw0 = tap0 % 3;
        const int kh1 = tap1 / 3, kw1 = tap1 % 3;

        uint32_t a0 = xsb[kh0][q][m0 + kw0];
        uint32_t a1 = xsb[kh0][q][m0 + 8 + kw0];
        uint32_t a2 = xsb[kh1][q][m0 + kw1];
        uint32_t a3 = xsb[kh1][q][m0 + 8 + kw1];

        const uint4* wp = wf_lane + step * (32 * 5);
        uint4 B0 = wp[0], B1 = wp[1], B2 = wp[2], B3 = wp[3];

        mma_bf16(acc[0], a0, a1, a2, a3, B0.x, B0.y);
        mma_bf16(acc[1], a0, a1, a2, a3, B0.z, B0.w);
        mma_bf16(acc[2], a0, a1, a2, a3, B1.x, B1.y);
        mma_bf16(acc[3], a0, a1, a2, a3, B1.z, B1.w);
        mma_bf16(acc[4], a0, a1, a2, a3, B2.x, B2.y);
        mma_bf16(acc[5], a0, a1, a2, a3, B2.z, B2.w);
        mma_bf16(acc[6], a0, a1, a2, a3, B3.x, B3.y);
        mma_bf16(acc[7], a0, a1, a2, a3, B3.z, B3.w);
    }

    // ---- epilogue: nonlinearities (tanh-based sigmoid) + STG.128 AoS store
    float local_logD = 0.f;
    #pragma unroll
    for (int pi = 0; pi < 2; ++pi) {
        int wglob = w0 + m0 + 8 * pi;
        #pragma unroll
        for (int ti = 0; ti < 2; ++ti) {
            int t = 2 * q + ti;
            int cidx = 2 * pi + ti;
            float a0v = acc[0][cidx];   // kappa
            float a1v = acc[1][cidx];   // m1
            float a2v = acc[2][cidx];   // m2
            float a3v = acc[3][cidx];   // Hxx
            float a4v = acc[4][cidx];   // Hxy
            float a5v = acc[5][cidx];   // Hyx
            float a6v = acc[6][cidx];   // Hyy
            float a7v = acc[7][cidx];   // tau

            float kap  = 0.99f * sigmoid_fast(a0v) + 0.01f;
            float kap2 = kap * kap;
            float hxx  = 0.99f * sigmoid_fast(a3v) + 0.01f;
            float hyy  = 0.99f * sigmoid_fast(a6v) + 0.01f;
            float hxys = 0.1f * (tanh_fast(a4v) + tanh_fast(a5v));
            float tau  = 9.9f * sigmoid_fast(a7v) + 0.1f;
            float Dv   = 1.f / (tau * tau);
            local_logD += -2.f * __logf(tau);

            float cc = kap2 + 2.f * hxx + 2.f * hyy;
            float ce =  0.5f * a1v - hxx;
            float cw = -0.5f * a1v - hxx;
            float cs =  0.5f * a2v - hyy;
            float cn = -0.5f * a2v - hyy;
            float cx = -0.25f * hxys;

            __nv_bfloat162 v0 = __floats2bfloat162_rn(cc, ce);
            __nv_bfloat162 v1 = __floats2bfloat162_rn(cw, cs);
            __nv_bfloat162 v2 = __floats2bfloat162_rn(cn, cx);
            __nv_bfloat162 v3 = __floats2bfloat162_rn(Dv, 0.f);
            uint4 pk;
            pk.x = *(uint32_t*)&v0;
            pk.y = *(uint32_t*)&v1;
            pk.z = *(uint32_t*)&v2;
            pk.w = *(uint32_t*)&v3;

            int idx = ((b * Tn + t) * Hn + h) * Wn + wglob;
            *(uint4*)(g_paramsB + (size_t)idx * 8) = pk;
        }
    }

    __syncthreads();
    float s = block_reduce_sum(local_logD);
    if (tid == 0)
        g_partLogD[(blockIdx.z * 256 + blockIdx.y) * 2 + blockIdx.x] = s;
}

// ---------------------------------------------------------------------------
// Fused double stencil (AoS bf16 params) + last-block final reduction.
// ---------------------------------------------------------------------------
__global__ __launch_bounds__(256)
void fused_stencil_kernel(const float* __restrict__ x, float* __restrict__ out) {
    __shared__ float xs[36][36];
    __shared__ float ys[34][34];

    const int tid = threadIdx.x;
    const int tx  = tid & 31;
    const int ty  = tid >> 5;
    const int bt  = blockIdx.z;        // b*T + t
    const int t   = bt & (Tn - 1);
    const int h0  = blockIdx.y * 32;
    const int w0  = blockIdx.x * 32;
    const int base = bt * Hn * Wn;

    const float* up = x + base;
    for (int i = tid; i < 36 * 36; i += 256) {
        int ly = i / 36, lx = i - ly * 36;
        int gh = h0 - 2 + ly, gw = w0 - 2 + lx;
        xs[ly][lx] = ((unsigned)gh < (unsigned)Hn && (unsigned)gw < (unsigned)Wn)
                         ? up[gh * Wn + gw] : 0.f;
    }
    __syncthreads();

    for (int i = tid; i < 34 * 34; i += 256) {
        int ly = i / 34, lx = i - ly * 34;
        int gh = h0 - 1 + ly, gw = w0 - 1 + lx;
        float yv = 0.f;
        if ((unsigned)gh < (unsigned)Hn && (unsigned)gw < (unsigned)Wn) {
            int gidx = base + gh * Wn + gw;
            uint4 pk = *(const uint4*)(g_paramsB + (size_t)gidx * 8);
            float2 f0 = __bfloat1622float2(*(__nv_bfloat162*)&pk.x);   // cc, ce
            float2 f1 = __bfloat1622float2(*(__nv_bfloat162*)&pk.y);   // cw, cs
            float2 f2 = __bfloat1622float2(*(__nv_bfloat162*)&pk.z);   // cn, cx

            float c  = xs[ly + 1][lx + 1];
            float e  = xs[ly + 1][lx + 2];
            float wv = xs[ly + 1][lx + 0];
            float s  = xs[ly + 2][lx + 1];
            float n  = xs[ly + 0][lx + 1];
            float se = xs[ly + 2][lx + 2];
            float ne = xs[ly + 0][lx + 2];
            float sw = xs[ly + 2][lx + 0];
            float nw = xs[ly + 0][lx + 0];

            yv = f0.x * c + f0.y * e + f1.x * wv + f1.y * s + f2.x * n
               + f2.y * (se - ne - sw + nw);
        }
        ys[ly][lx] = yv;
    }
    __syncthreads();

    float local = 0.f;
    #pragma unroll
    for (int r = 0; r < 4; ++r) {
        int iy = ty * 4 + r;
        int gh = h0 + iy, gw = w0 + tx;
        int gidx = base + gh * Wn + gw;
        int ly = iy + 1, lx = tx + 1;

        uint4 pk = *(const uint4*)(g_paramsB + (size_t)gidx * 8);
        float2 f0 = __bfloat1622float2(*(__nv_bfloat162*)&pk.x);   // cc, ce
        float2 f1 = __bfloat1622float2(*(__nv_bfloat162*)&pk.y);   // cw, cs
        float2 f2 = __bfloat1622float2(*(__nv_bfloat162*)&pk.z);   // cn, cx
        float2 f3 = __bfloat1622float2(*(__nv_bfloat162*)&pk.w);   // D, pad

        float c  = ys[ly][lx];
        float e  = ys[ly][lx + 1];
        float wv = ys[ly][lx - 1];
        float s  = ys[ly + 1][lx];
        float n  = ys[ly - 1][lx];
        float se = ys[ly + 1][lx + 1];
        float ne = ys[ly - 1][lx + 1];
        float sw = ys[ly + 1][lx - 1];
        float nw = ys[ly - 1][lx - 1];

        float z = f0.x * c + f0.y * e + f1.x * wv + f1.y * s + f2.x * n
                + f2.y * (se - ne - sw + nw);

        float xc    = xs[iy + 2][tx + 2];
        float xprev = (t > 0) ? x[gidx - Hn * Wn] : 0.f;
        float rr = xc + z - xprev;
        local += f3.x * rr * rr;
    }

    __syncthreads();
    float ssum = block_reduce_sum(local);

    __shared__ bool amLast;
    if (tid == 0) {
        g_partXQX[(blockIdx.z * 8 + blockIdx.y) * 8 + blockIdx.x] = ssum;
        __threadfence();
        unsigned v = atomicAdd(&g_ticket, 1u);
        amLast = (v == STENCIL_CTAS - 1);
    }
    __syncthreads();

    if (amLast) {
        __shared__ double redq[256];
        __shared__ double redl[256];
        double xq = 0.0, ld = 0.0;
        #pragma unroll
        for (int j = 0; j < STENCIL_CTAS / 256; ++j)
            xq += (double)g_partXQX[tid + 256 * j];
        #pragma unroll
        for (int j = 0; j < CONV_CTAS / 256; ++j)
            ld += (double)g_partLogD[tid + 256 * j];
        redq[tid] = xq;
        redl[tid] = ld;
        __syncthreads();
        #pragma unroll
        for (int o = 128; o > 0; o >>= 1) {
            if (tid < o) {
                redq[tid] += redq[tid + o];
                redl[tid] += redl[tid + o];
            }
            __syncthreads();
        }
        if (tid == 0) out[0] = (float)(0.5 * (redq[0] - redl[0]));
    }
}

extern "C" void kernel_launch(void* const* d_in, const int* in_sizes, int n_in,
                              void* d_out, int out_size) {
    const float* x = (const float*)d_in[0];
    const float* w = (const float*)d_in[1];
    float* out = (float*)d_out;

    precompute_wf_kernel<<<13, 256>>>(w);
    conv_mma_kernel<<<dim3(2, 256, Bn), 256>>>(x, w);
    fused_stencil_kernel<<<dim3(8, 8, Bn * Tn), 256>>>(x, out);
}

// round 15
// speedup vs baseline: 1.2461x; 1.0548x over previous
#include <cuda_runtime.h>
#include <cuda_bf16.h>
#include <math.h>
#include <stdint.h>

#define Bn 4
#define Tn 8
#define Hn 256
#define Wn 256
#define Nn (Bn*Tn*Hn*Wn)   // 2,097,152

#define STENCIL_CTAS 2048
#define CONV_CTAS    2048

// AoS params: per point 8 bf16 = 16 B: cc,ce,cw,cs,cn,cx,D,pad
__device__ __nv_bfloat16 g_paramsB[(size_t)Nn * 8];
__device__ float g_partLogD[CONV_CTAS];
__device__ float g_partXQX[STENCIL_CTAS];
__device__ uint32_t g_Wfb[5 * 32 * 20];  // per-lane bf16x2 B fragments (5 k16 steps)
__device__ unsigned g_ticket;

__device__ __forceinline__ float tanh_fast(float x) {
    float y; asm("tanh.approx.f32 %0, %1;" : "=f"(y) : "f"(x)); return y;
}
__device__ __forceinline__ float sigmoid_fast(float x) {
    return fmaf(0.5f, tanh_fast(0.5f * x), 0.5f);
}
__device__ __forceinline__ void mma_bf16(float c[4],
                                         uint32_t a0, uint32_t a1, uint32_t a2, uint32_t a3,
                                         uint32_t b0, uint32_t b1) {
    asm("mma.sync.aligned.m16n8k16.row.col.f32.bf16.bf16.f32 "
        "{%0,%1,%2,%3}, {%4,%5,%6,%7}, {%8,%9}, {%0,%1,%2,%3};"
        : "+f"(c[0]), "+f"(c[1]), "+f"(c[2]), "+f"(c[3])
        : "r"(a0), "r"(a1), "r"(a2), "r"(a3), "r"(b0), "r"(b1));
}

__device__ __forceinline__ float block_reduce_sum(float v) {
    __shared__ float red[8];
    #pragma unroll
    for (int o = 16; o > 0; o >>= 1) v += __shfl_down_sync(0xffffffffu, v, o);
    int lane = threadIdx.x & 31, wid = threadIdx.x >> 5;
    if (lane == 0) red[wid] = v;
    __syncthreads();
    if (wid == 0) {
        v = (lane < 8) ? red[lane] : 0.f;
        #pragma unroll
        for (int o = 4; o > 0; o >>= 1) v += __shfl_down_sync(0xffffffffu, v, o);
    }
    return v;  // valid on thread 0
}

// ---------------------------------------------------------------------------
// Weight fragment swizzle (bf16x2, tap pairs) + ticket reset.
// ---------------------------------------------------------------------------
__global__ void precompute_wf_kernel(const float* __restrict__ w) {
    int j = blockIdx.x * 256 + threadIdx.x;
    if (j == 0) g_ticket = 0;
    if (j < 5 * 32 * 16) {
        int step = j >> 9;
        int r    = j & 511;
        int ln   = r >> 4;
        int e    = r & 15;
        int n    = e >> 1;
        int s    = e & 1;
        int q    = ln & 3;
        int ocg  = ln >> 2;
        int oc   = n * 8 + ocg;
        int tap  = step * 2 + s;
        float w0 = 0.f, w1 = 0.f;
        if (tap < 9) {
            w0 = w[oc * 72 + (2 * q)     * 9 + tap];
            w1 = w[oc * 72 + (2 * q + 1) * 9 + tap];
        }
        __nv_bfloat162 pk = __floats2bfloat162_rn(w0, w1);
        g_Wfb[(step * 32 + ln) * 20 + e] = *(uint32_t*)&pk;
    } else if (j < 5 * 32 * 16 + 5 * 32 * 4) {
        int p  = j - 5 * 32 * 16;
        int tl = p >> 2;
        int e  = 16 + (p & 3);
        g_Wfb[tl * 20 + e] = 0;
    }
}

// ---------------------------------------------------------------------------
// Conv 3x3 (8 -> 64 ch), bf16 mma.sync m16n8k16 — frozen R14 config.
// ---------------------------------------------------------------------------
__global__ __launch_bounds__(256)
void conv_mma_kernel(const float* __restrict__ x, const float* __restrict__ w) {
    __shared__ uint32_t xsb[3][4][136];                    // bf16x2 ic-pairs
    __shared__ __align__(16) uint32_t Wfb[5 * 32 * 20];    // per-lane B frags

    const int tid  = threadIdx.x;
    const int lane = tid & 31;
    const int wid  = tid >> 5;
    const int seg  = blockIdx.x;           // 0..1
    const int h    = blockIdx.y;           // 0..255
    const int b    = blockIdx.z;           // 0..3
    const int w0   = seg * 128;

    // ---- stage weights: pure linear copy (800 uint4) ----
    {
        const uint4* src = (const uint4*)g_Wfb;
        uint4* dst = (uint4*)Wfb;
        #pragma unroll
        for (int j = 0; j < 4; ++j) {
            int i = tid + j * 256;
            if (i < 800) dst[i] = src[i];
        }
    }

    // ---- stage x slab: 12 rows (kh 0..2 x icpair 0..3) x 130 cols ----
    {
        const float* xb = x + b * Tn * Hn * Wn;
        #pragma unroll
        for (int rr = 0; rr < 2; ++rr) {
            int row = wid + rr * 8;        // 0..15, only <12 valid
            if (row < 12) {
                int kh = row >> 2;
                int p  = row & 3;
                int gh = h - 1 + kh;
                bool hok = (unsigned)gh < (unsigned)Hn;
                const float* rp0 = xb + ((2 * p)     * Hn + gh) * Wn;
                const float* rp1 = xb + ((2 * p + 1) * Hn + gh) * Wn;
                #pragma unroll
                for (int it = 0; it < 5; ++it) {
                    int col = lane + it * 32;
                    if (col < 130) {
                        int gw = w0 - 1 + col;
                        bool ok = hok && (unsigned)gw < (unsigned)Wn;
                        float v0 = ok ? rp0[gw] : 0.f;
                        float v1 = ok ? rp1[gw] : 0.f;
                        __nv_bfloat162 pk = __floats2bfloat162_rn(v0, v1);
                        xsb[kh][p][col] = *(uint32_t*)&pk;
                    }
                }
            }
        }
    }
    __syncthreads();

    // ---- GEMM: each warp m16 x n64, K=80 (5 k16 steps, last half zero) ----
    const int q  = lane & 3;
    const int m0 = (wid << 4) + (lane >> 2);

    float acc[8][4];
    #pragma unroll
    for (int n = 0; n < 8; ++n)
        #pragma unroll
        for (int c = 0; c < 4; ++c) acc[n][c] = 0.f;

    const uint4* wf_lane = (const uint4*)&Wfb[lane * 20];

    #pragma unroll
    for (int step = 0; step < 5; ++step) {
        const int tap0 = 2 * step;
        const int tap1 = (2 * step + 1 < 9) ? 2 * step + 1 : 8;  // tap9 -> B=0
        const int kh0 = tap0 / 3, kw0 = tap0 % 3;
        const int kh1 = tap1 / 3, kw1 = tap1 % 3;

        uint32_t a0 = xsb[kh0][q][m0 + kw0];
        uint32_t a1 = xsb[kh0][q][m0 + 8 + kw0];
        uint32_t a2 = xsb[kh1][q][m0 + kw1];
        uint32_t a3 = xsb[kh1][q][m0 + 8 + kw1];

        const uint4* wp = wf_lane + step * (32 * 5);
        uint4 B0 = wp[0], B1 = wp[1], B2 = wp[2], B3 = wp[3];

        mma_bf16(acc[0], a0, a1, a2, a3, B0.x, B0.y);
        mma_bf16(acc[1], a0, a1, a2, a3, B0.z, B0.w);
        mma_bf16(acc[2], a0, a1, a2, a3, B1.x, B1.y);
        mma_bf16(acc[3], a0, a1, a2, a3, B1.z, B1.w);
        mma_bf16(acc[4], a0, a1, a2, a3, B2.x, B2.y);
        mma_bf16(acc[5], a0, a1, a2, a3, B2.z, B2.w);
        mma_bf16(acc[6], a0, a1, a2, a3, B3.x, B3.y);
        mma_bf16(acc[7], a0, a1, a2, a3, B3.z, B3.w);
    }

    // ---- epilogue: nonlinearities (tanh-based sigmoid) + STG.128 AoS store
    float local_logD = 0.f;
    #pragma unroll
    for (int pi = 0; pi < 2; ++pi) {
        int wglob = w0 + m0 + 8 * pi;
        #pragma unroll
        for (int ti = 0; ti < 2; ++ti) {
            int t = 2 * q + ti;
            int cidx = 2 * pi + ti;
            float a0v = acc[0][cidx];   // kappa
            float a1v = acc[1][cidx];   // m1
            float a2v = acc[2][cidx];   // m2
            float a3v = acc[3][cidx];   // Hxx
            float a4v = acc[4][cidx];   // Hxy
            float a5v = acc[5][cidx];   // Hyx
            float a6v = acc[6][cidx];   // Hyy
            float a7v = acc[7][cidx];   // tau

            float kap  = 0.99f * sigmoid_fast(a0v) + 0.01f;
            float kap2 = kap * kap;
            float hxx  = 0.99f * sigmoid_fast(a3v) + 0.01f;
            float hyy  = 0.99f * sigmoid_fast(a6v) + 0.01f;
            float hxys = 0.1f * (tanh_fast(a4v) + tanh_fast(a5v));
            float tau  = 9.9f * sigmoid_fast(a7v) + 0.1f;
            float Dv   = 1.f / (tau * tau);
            local_logD += -2.f * __logf(tau);

            float cc = kap2 + 2.f * hxx + 2.f * hyy;
            float ce =  0.5f * a1v - hxx;
            float cw = -0.5f * a1v - hxx;
            float cs =  0.5f * a2v - hyy;
            float cn = -0.5f * a2v - hyy;
            float cx = -0.25f * hxys;

            __nv_bfloat162 v0 = __floats2bfloat162_rn(cc, ce);
            __nv_bfloat162 v1 = __floats2bfloat162_rn(cw, cs);
            __nv_bfloat162 v2 = __floats2bfloat162_rn(cn, cx);
            __nv_bfloat162 v3 = __floats2bfloat162_rn(Dv, 0.f);
            uint4 pk;
            pk.x = *(uint32_t*)&v0;
            pk.y = *(uint32_t*)&v1;
            pk.z = *(uint32_t*)&v2;
            pk.w = *(uint32_t*)&v3;

            int idx = ((b * Tn + t) * Hn + h) * Wn + wglob;
            *(uint4*)(g_paramsB + (size_t)idx * 8) = pk;
        }
    }

    __syncthreads();
    float s = block_reduce_sum(local_logD);
    if (tid == 0)
        g_partLogD[(blockIdx.z * 256 + blockIdx.y) * 2 + blockIdx.x] = s;
}

// ---------------------------------------------------------------------------
// Fused double stencil: phase-1 computes interior y with params held in regs
// for phase-2 (no duplicate param loads); ring handled by threads 0..131.
// ---------------------------------------------------------------------------
__global__ __launch_bounds__(256)
void fused_stencil_kernel(const float* __restrict__ x, float* __restrict__ out) {
    __shared__ float xs[36][36];
    __shared__ float ys[34][34];

    const int tid = threadIdx.x;
    const int tx  = tid & 31;
    const int ty  = tid >> 5;
    const int bt  = blockIdx.z;        // b*T + t
    const int t   = bt & (Tn - 1);
    const int h0  = blockIdx.y * 32;
    const int w0  = blockIdx.x * 32;
    const int base = bt * Hn * Wn;

    const float* up = x + base;
    for (int i = tid; i < 36 * 36; i += 256) {
        int ly = i / 36, lx = i - ly * 36;
        int gh = h0 - 2 + ly, gw = w0 - 2 + lx;
        xs[ly][lx] = ((unsigned)gh < (unsigned)Hn && (unsigned)gw < (unsigned)Wn)
                         ? up[gh * Wn + gw] : 0.f;
    }
    __syncthreads();

    // ---- phase 1a: interior y (4 points/thread); params kept in registers
    uint4 pk4[4];
    #pragma unroll
    for (int r = 0; r < 4; ++r) {
        int iy = ty * 4 + r;
        int ly = iy + 1, lx = tx + 1;
        int gidx = base + (h0 + iy) * Wn + (w0 + tx);
        pk4[r] = *(const uint4*)(g_paramsB + (size_t)gidx * 8);
        float2 f0 = __bfloat1622float2(*(__nv_bfloat162*)&pk4[r].x);   // cc, ce
        float2 f1 = __bfloat1622float2(*(__nv_bfloat162*)&pk4[r].y);   // cw, cs
        float2 f2 = __bfloat1622float2(*(__nv_bfloat162*)&pk4[r].z);   // cn, cx

        float c  = xs[ly + 1][lx + 1];
        float e  = xs[ly + 1][lx + 2];
        float wv = xs[ly + 1][lx + 0];
        float s  = xs[ly + 2][lx + 1];
        float n  = xs[ly + 0][lx + 1];
        float se = xs[ly + 2][lx + 2];
        float ne = xs[ly + 0][lx + 2];
        float sw = xs[ly + 2][lx + 0];
        float nw = xs[ly + 0][lx + 0];

        ys[ly][lx] = f0.x * c + f0.y * e + f1.x * wv + f1.y * s + f2.x * n
                   + f2.y * (se - ne - sw + nw);
    }

    // ---- phase 1b: ring y (132 points, threads 0..131)
    if (tid < 132) {
        int ly, lx;
        if (tid < 34)        { ly = 0;         lx = tid; }
        else if (tid < 68)   { ly = 33;        lx = tid - 34; }
        else if (tid < 100)  { ly = tid - 67;  lx = 0; }     // ly 1..32
        else                 { ly = tid - 99;  lx = 33; }    // ly 1..32
        int gh = h0 - 1 + ly, gw = w0 - 1 + lx;
        float yv = 0.f;
        if ((unsigned)gh < (unsigned)Hn && (unsigned)gw < (unsigned)Wn) {
            int gidx = base + gh * Wn + gw;
            uint4 pk = *(const uint4*)(g_paramsB + (size_t)gidx * 8);
            float2 f0 = __bfloat1622float2(*(__nv_bfloat162*)&pk.x);
            float2 f1 = __bfloat1622float2(*(__nv_bfloat162*)&pk.y);
            float2 f2 = __bfloat1622float2(*(__nv_bfloat162*)&pk.z);

            float c  = xs[ly + 1][lx + 1];
            float e  = xs[ly + 1][lx + 2];
            float wv = xs[ly + 1][lx + 0];
            float s  = xs[ly + 2][lx + 1];
            float n  = xs[ly + 0][lx + 1];
            float se = xs[ly + 2][lx + 2];
            float ne = xs[ly + 0][lx + 2];
            float sw = xs[ly + 2][lx + 0];
            float nw = xs[ly + 0][lx + 0];

            yv = f0.x * c + f0.y * e + f1.x * wv + f1.y * s + f2.x * n
               + f2.y * (se - ne - sw + nw);
        }
        ys[ly][lx] = yv;
    }
    __syncthreads();

    // ---- phase 2: z = A(y) on interior with register-resident params
    float local = 0.f;
    #pragma unroll
    for (int r = 0; r < 4; ++r) {
        int iy = ty * 4 + r;
        int gh = h0 + iy, gw = w0 + tx;
        int gidx = base + gh * Wn + gw;
        int ly = iy + 1, lx = tx + 1;

        float2 f0 = __bfloat1622float2(*(__nv_bfloat162*)&pk4[r].x);   // cc, ce
        float2 f1 = __bfloat1622float2(*(__nv_bfloat162*)&pk4[r].y);   // cw, cs
        float2 f2 = __bfloat1622float2(*(__nv_bfloat162*)&pk4[r].z);   // cn, cx
        float2 f3 = __bfloat1622float2(*(__nv_bfloat162*)&pk4[r].w);   // D, pad

        float c  = ys[ly][lx];
        float e  = ys[ly][lx + 1];
        float wv = ys[ly][lx - 1];
        float s  = ys[ly + 1][lx];
        float n  = ys[ly - 1][lx];
        float se = ys[ly + 1][lx + 1];
        float ne = ys[ly - 1][lx + 1];
        float sw = ys[ly + 1][lx - 1];
        float nw = ys[ly - 1][lx - 1];

        float z = f0.x * c + f0.y * e + f1.x * wv + f1.y * s + f2.x * n
                + f2.y * (se - ne - sw + nw);

        float xc    = xs[iy + 2][tx + 2];
        float xprev = (t > 0) ? x[gidx - Hn * Wn] : 0.f;
        float rr = xc + z - xprev;
        local += f3.x * rr * rr;
    }

    __syncthreads();
    float ssum = block_reduce_sum(local);

    __shared__ bool amLast;
    if (tid == 0) {
        g_partXQX[(blockIdx.z * 8 + blockIdx.y) * 8 + blockIdx.x] = ssum;
        __threadfence();
        unsigned v = atomicAdd(&g_ticket, 1u);
        amLast = (v == STENCIL_CTAS - 1);
    }
    __syncthreads();

    if (amLast) {
        __shared__ double redq[256];
        __shared__ double redl[256];
        double xq = 0.0, ld = 0.0;
        #pragma unroll
        for (int j = 0; j < STENCIL_CTAS / 256; ++j)
            xq += (double)g_partXQX[tid + 256 * j];
        #pragma unroll
        for (int j = 0; j < CONV_CTAS / 256; ++j)
            ld += (double)g_partLogD[tid + 256 * j];
        redq[tid] = xq;
        redl[tid] = ld;
        __syncthreads();
        #pragma unroll
        for (int o = 128; o > 0; o >>= 1) {
            if (tid < o) {
                redq[tid] += redq[tid + o];
                redl[tid] += redl[tid + o];
            }
            __syncthreads();
        }
        if (tid == 0) out[0] = (float)(0.5 * (redq[0] - redl[0]));
    }
}

extern "C" void kernel_launch(void* const* d_in, const int* in_sizes, int n_in,
                              void* d_out, int out_size) {
    const float* x = (const float*)d_in[0];
    const float* w = (const float*)d_in[1];
    float* out = (float*)d_out;

    precompute_wf_kernel<<<13, 256>>>(w);
    conv_mma_kernel<<<dim3(2, 256, Bn), 256>>>(x, w);
    fused_stencil_kernel<<<dim3(8, 8, Bn * Tn), 256>>>(x, out);
}